// round 15
// baseline (speedup 1.0000x reference)
#include <cuda_runtime.h>

// ---------------------------------------------------------------------------
// B=512, NQ=10, NA=4, T=16, DEG=4, LAYERS=2.
// Round-14 champion layout: 512 threads/CTA = 16 warps; warp w owns ancilla
// slice t=w; 1024 amps/warp = 32 f2x regs/lane. Alternating qubit map:
//   qubit Q even -> register bit Q/2 ; qubit Q odd -> lane bit Q/2.
// Ancilla mix M_k = alpha_k I + beta_k u0 u0^dag (rank-1).
// ry-merge: final adjoint ry block merged with qff's opening ry block.
// New this round: gate constants pre-packed as {(c,c),(s,s)} ulonglong2;
// sign variants derived by 64-bit XOR instead of pack/negate MOV chains.
// ---------------------------------------------------------------------------

#define BATCH 512

typedef unsigned long long f2x;

#define SGN_BOTH 0x8000000080000000ULL  // negate both f32 halves
#define SGN_HI   0x8000000000000000ULL  // negate hi half (second pack arg)
#define SGN_LO   0x0000000080000000ULL  // negate lo half (first pack arg)

__device__ ulonglong2 g_csp[BATCH * 1280];  // packed {(c,c),(s,s)} per (b,t,gate)
__device__ ulonglong2 g_qffp[40];           // packed qff constants
__device__ float2 g_v0[16];                 // e^{i phi0} * U[:,0]
__device__ float2 g_u0[16];                 // U[:,0]
__device__ float4 g_ab[3];                  // (cos phi, -sin phi, 2 sin phi, 0)

// ---- f32x2 primitives ------------------------------------------------------
static __device__ __forceinline__ f2x f2pack(float lo, float hi) {
    f2x r; asm("mov.b64 %0, {%1, %2};" : "=l"(r) : "f"(lo), "f"(hi)); return r;
}
static __device__ __forceinline__ void f2unpack(f2x v, float& lo, float& hi) {
    asm("mov.b64 {%0, %1}, %2;" : "=f"(lo), "=f"(hi) : "l"(v));
}
static __device__ __forceinline__ float f2lo(f2x v) {
    float lo, hi; f2unpack(v, lo, hi); return lo;
}
static __device__ __forceinline__ f2x f2fma(f2x a, f2x b, f2x c) {
    f2x r; asm("fma.rn.f32x2 %0, %1, %2, %3;" : "=l"(r) : "l"(a), "l"(b), "l"(c)); return r;
}
static __device__ __forceinline__ f2x f2mul(f2x a, f2x b) {
    f2x r; asm("mul.rn.f32x2 %0, %1, %2;" : "=l"(r) : "l"(a), "l"(b)); return r;
}
static __device__ __forceinline__ f2x f2add(f2x a, f2x b) {
    f2x r; asm("add.rn.f32x2 %0, %1, %2;" : "=l"(r) : "l"(a), "l"(b)); return r;
}
static __device__ __forceinline__ f2x f2swap(f2x v) {
    float lo, hi; f2unpack(v, lo, hi); return f2pack(hi, lo);
}
static __device__ __forceinline__ f2x f2shfl(f2x v, int m) {
    float lo, hi; f2unpack(v, lo, hi);
    lo = __shfl_xor_sync(0xffffffffu, lo, m);
    hi = __shfl_xor_sync(0xffffffffu, hi, m);
    return f2pack(lo, hi);
}
static __device__ __forceinline__ f2x f2shflswap(f2x v, int m) {
    float lo, hi; f2unpack(v, lo, hi);
    lo = __shfl_xor_sync(0xffffffffu, lo, m);
    hi = __shfl_xor_sync(0xffffffffu, hi, m);
    return f2pack(hi, lo);
}
static __device__ __forceinline__ float2 cmulf(float2 a, float2 b) {
    return make_float2(a.x * b.x - a.y * b.y, a.x * b.y + a.y * b.x);
}

// ---- gates (round-9/14 forms; measured best) --------------------------------
template <int Q>
static __device__ __forceinline__ void ry_g(f2x* s, f2x cc, f2x sp, f2x ns, int lane) {
    if constexpr ((Q & 1) == 0) {
        constexpr int M = 1 << (Q / 2);
#pragma unroll
        for (int r = 0; r < 32; ++r)
            if (!(r & M)) {
                f2x a = s[r], b = s[r | M];
                s[r]     = f2fma(cc, a, f2mul(ns, b));
                s[r | M] = f2fma(cc, b, f2mul(sp, a));
            }
    } else {
        constexpr int L = 1 << (Q / 2);
        const f2x t = (lane & L) ? sp : ns;
#pragma unroll
        for (int r = 0; r < 32; ++r) {
            f2x o = f2shfl(s[r], L);
            s[r] = f2fma(cc, s[r], f2mul(t, o));
        }
    }
}

// crx (ctrl=1): new = c*own + sn*(other.y, -other.x); pk = (sn, -sn).
template <int C, int TQ>
static __device__ __forceinline__ void crx_g(f2x* s, f2x cc, f2x pk, int lane) {
    if constexpr ((C & 1) == 0 && (TQ & 1) == 1) {        // reg ctrl, lane tgt
        constexpr int MC = 1 << (C / 2), LT = 1 << (TQ / 2);
#pragma unroll
        for (int r = 0; r < 32; ++r)
            if (r & MC) {  // compile-time per r: shfl warp-uniform
                f2x osw = f2shflswap(s[r], LT);
                s[r] = f2fma(cc, s[r], f2mul(pk, osw));
            }
    } else {                                              // lane ctrl, reg tgt: no shfl
        constexpr int LC = 1 << (C / 2), MT = 1 << (TQ / 2);
        const bool act = (lane & LC) != 0;
        const f2x cc2 = act ? cc : f2pack(1.f, 1.f);
        const f2x pk2 = act ? pk : 0ull;
#pragma unroll
        for (int r = 0; r < 32; ++r)
            if (!(r & MT)) {
                f2x a = s[r], b = s[r | MT];
                s[r]      = f2fma(cc2, a, f2mul(pk2, f2swap(b)));
                s[r | MT] = f2fma(cc2, b, f2mul(pk2, f2swap(a)));
            }
    }
}

// ---- gate lists (order/indices validated rounds 4-14) ----------------------
// Packed table: cs[I].x = (c,c), cs[I].y = (s,s). Sign variants via XOR.
#define RYM_F(Q, I)  { ulonglong2 u = cs[I]; \
                       ry_g<Q>(s, u.x, u.y, u.y ^ SGN_BOTH, lane); }
#define RYM_A(Q, I)  { ulonglong2 u = cs[I]; \
                       ry_g<Q>(s, u.x, u.y ^ SGN_BOTH, u.y, lane); }
#define CRXM_F(C, T, I) { ulonglong2 u = cs[I]; \
                          crx_g<C, T>(s, u.x, u.y ^ SGN_HI, lane); }
#define CRXM_A(C, T, I) { ulonglong2 u = cs[I]; \
                          crx_g<C, T>(s, u.x, u.y ^ SGN_LO, lane); }
// Merged ry: ry(phi_qff) * ry(-theta_sel) = ry(phi - theta). Scalars extracted
// from packed tables (10 gates, once per kernel -- negligible).
#define RYM_C(Q, I)  { float ca = f2lo(cs[I].x), sa2 = f2lo(cs[I].y);             \
                       float cb = f2lo(csq[I].x), sb = f2lo(csq[I].y);            \
                       float cm = fmaf(cb, ca, sb * sa2);                         \
                       float sm = fmaf(sb, ca, -cb * sa2);                        \
                       ry_g<Q>(s, f2pack(cm, cm), f2pack(sm, sm),                 \
                               f2pack(-sm, -sm), lane); }

#define GATES_TAIL(RYM, CRXM)                                                    \
    CRXM(9, 0, 10) CRXM(8, 9, 11) CRXM(7, 8, 12) CRXM(6, 7, 13) CRXM(5, 6, 14)  \
    CRXM(4, 5, 15) CRXM(3, 4, 16) CRXM(2, 3, 17) CRXM(1, 2, 18) CRXM(0, 1, 19)  \
    RYM(0, 20) RYM(1, 21) RYM(2, 22) RYM(3, 23) RYM(4, 24)                       \
    RYM(5, 25) RYM(6, 26) RYM(7, 27) RYM(8, 28) RYM(9, 29)                       \
    CRXM(9, 8, 30) CRXM(0, 9, 31) CRXM(1, 0, 32) CRXM(2, 1, 33) CRXM(3, 2, 34)  \
    CRXM(4, 3, 35) CRXM(5, 4, 36) CRXM(6, 5, 37) CRXM(7, 6, 38) CRXM(8, 7, 39)

#define GATES_FWD(RYM, CRXM)                                                     \
    RYM(0, 0) RYM(1, 1) RYM(2, 2) RYM(3, 3) RYM(4, 4)                            \
    RYM(5, 5) RYM(6, 6) RYM(7, 7) RYM(8, 8) RYM(9, 9)                            \
    GATES_TAIL(RYM, CRXM)

// Adjoint layer WITHOUT the trailing block-1 rys (merges into qff).
#define GATES_ADJ_NOB1(RYM, CRXM)                                                \
    CRXM(8, 7, 39) CRXM(7, 6, 38) CRXM(6, 5, 37) CRXM(5, 4, 36) CRXM(4, 3, 35)  \
    CRXM(3, 2, 34) CRXM(2, 1, 33) CRXM(1, 0, 32) CRXM(0, 9, 31) CRXM(9, 8, 30)  \
    RYM(9, 29) RYM(8, 28) RYM(7, 27) RYM(6, 26) RYM(5, 25)                       \
    RYM(4, 24) RYM(3, 23) RYM(2, 22) RYM(1, 21) RYM(0, 20)                       \
    CRXM(0, 1, 19) CRXM(1, 2, 18) CRXM(2, 3, 17) CRXM(3, 4, 16) CRXM(4, 5, 15)  \
    CRXM(5, 6, 14) CRXM(6, 7, 13) CRXM(7, 8, 12) CRXM(8, 9, 11) CRXM(9, 0, 10)

#define GATES_ADJ(RYM, CRXM)                                                     \
    GATES_ADJ_NOB1(RYM, CRXM)                                                    \
    RYM(9, 9) RYM(8, 8) RYM(7, 7) RYM(6, 6) RYM(5, 5)                            \
    RYM(4, 4) RYM(3, 3) RYM(2, 2) RYM(1, 1) RYM(0, 0)

static __device__ __forceinline__ void run_layer_fwd(f2x* s, const ulonglong2* cs, int lane) {
    GATES_FWD(RYM_F, CRXM_F)
}
static __device__ __forceinline__ void run_layer_fwd_tail(f2x* s, const ulonglong2* cs, int lane) {
    GATES_TAIL(RYM_F, CRXM_F)
}
static __device__ __forceinline__ void run_layer_adj(f2x* s, const ulonglong2* cs, int lane) {
    GATES_ADJ(RYM_A, CRXM_A)
}
static __device__ __forceinline__ void run_layer_adj_nob1(f2x* s, const ulonglong2* cs, int lane) {
    GATES_ADJ_NOB1(RYM_A, CRXM_A)
}
// qff with opening ry block merged with preceding adjoint block-1.
static __device__ __forceinline__ void run_qff_merged(f2x* s, const ulonglong2* csSel,
                                                      const ulonglong2* csq, int lane) {
    {
        const ulonglong2* cs = csSel;
        RYM_C(0, 0) RYM_C(1, 1) RYM_C(2, 2) RYM_C(3, 3) RYM_C(4, 4)
        RYM_C(5, 5) RYM_C(6, 6) RYM_C(7, 7) RYM_C(8, 8) RYM_C(9, 9)
    }
    {
        const ulonglong2* cs = csq;
        GATES_TAIL(RYM_F, CRXM_F)
    }
}

// ---- expectation values ----------------------------------------------------
template <int Q>
static __device__ __forceinline__ void expval_q(const f2x* s, int lane, float* acc) {
    float ax = 0.f, ay = 0.f, z = 0.f;
    if constexpr ((Q & 1) == 0) {
        constexpr int M = 1 << (Q / 2);
#pragma unroll
        for (int r = 0; r < 32; ++r)
            if (!(r & M)) {
                float axr, ayr, bxr, byr;
                f2unpack(s[r], axr, ayr);
                f2unpack(s[r | M], bxr, byr);
                ax = fmaf(axr, bxr, fmaf(ayr, byr, ax));
                ay = fmaf(axr, byr, fmaf(-ayr, bxr, ay));
                z  = fmaf(axr, axr, fmaf(ayr, ayr, fmaf(-bxr, bxr, fmaf(-byr, byr, z))));
            }
    } else {
        constexpr int L = 1 << (Q / 2);
        const bool lo = (lane & L) == 0;
#pragma unroll
        for (int r = 0; r < 32; ++r) {
            float x, y;
            f2unpack(s[r], x, y);
            float ox = __shfl_xor_sync(0xffffffffu, x, L);
            float oy = __shfl_xor_sync(0xffffffffu, y, L);
            float n = fmaf(x, x, y * y);
            if (lo) {
                ax = fmaf(x, ox, fmaf(y, oy, ax));
                ay = fmaf(x, oy, fmaf(-y, ox, ay));
                z += n;
            } else {
                z -= n;
            }
        }
    }
#pragma unroll
    for (int off = 16; off; off >>= 1) {
        ax += __shfl_xor_sync(0xffffffffu, ax, off);
        ay += __shfl_xor_sync(0xffffffffu, ay, off);
        z  += __shfl_xor_sync(0xffffffffu, z, off);
    }
    if (lane == 0) {
        atomicAdd(&acc[Q], 2.f * ax);
        atomicAdd(&acc[10 + Q], 2.f * ay);
        atomicAdd(&acc[20 + Q], z);
    }
}

// ---------------------------------------------------------------------------
// Projection kernel (circuit-constant setup in block 0)
// ---------------------------------------------------------------------------
__global__ void qts_proj(const float* __restrict__ x, const float* __restrict__ Wp,
                         const float* __restrict__ bp, const float* __restrict__ prep,
                         const float* __restrict__ sig, const float* __restrict__ qff) {
    __shared__ float xe[16][64];
    __shared__ float WsT[64][80];
    __shared__ float2 U[16][16];
    int b = blockIdx.x, tid = threadIdx.x;

    if (b == 0) {
        if (tid < 16) {
            float2 v[16];
            for (int t = 0; t < 16; ++t) v[t] = make_float2(t == tid ? 1.f : 0.f, 0.f);
            for (int ly = 0; ly < 4; ++ly) {
                for (int qi = 0; qi < 4; ++qi) {
                    int m = 1 << (3 - qi);
                    float th = prep[(ly * 4 + qi) * 2 + 0];
                    float c, sn;
                    sincosf(0.5f * th, &sn, &c);
                    for (int j = 0; j < 16; ++j)
                        if (!(j & m)) {
                            float2 a0 = v[j], a1 = v[j | m];
                            v[j]     = make_float2(c * a0.x - sn * a1.x, c * a0.y - sn * a1.y);
                            v[j | m] = make_float2(sn * a0.x + c * a1.x, sn * a0.y + c * a1.y);
                        }
                    th = prep[(ly * 4 + qi) * 2 + 1];
                    sincosf(0.5f * th, &sn, &c);
                    float2 e0 = make_float2(c, -sn), e1 = make_float2(c, sn);
                    for (int j = 0; j < 16; ++j) v[j] = cmulf(v[j], (j & m) ? e1 : e0);
                }
                for (int i = 0; i < 3; ++i) {
                    int cm = 1 << (3 - i), tm = 1 << (2 - i);
                    for (int j = 0; j < 16; ++j)
                        if ((j & cm) && !(j & tm)) {
                            float2 tmp = v[j]; v[j] = v[j | tm]; v[j | tm] = tmp;
                        }
                }
            }
            for (int t = 0; t < 16; ++t) U[t][tid] = v[t];
        }
        __syncthreads();
        if (tid < 16) {
            float c, sn;
            sincosf(sig[0], &sn, &c);
            g_v0[tid] = cmulf(make_float2(c, sn), U[tid][0]);
            g_u0[tid] = U[tid][0];
        }
        if (tid < 40) {
            float c, sn;
            sincosf(0.5f * qff[tid], &sn, &c);
            g_qffp[tid] = make_ulonglong2(f2pack(c, c), f2pack(sn, sn));
        }
        if (tid < 3) {
            float c, sn;
            sincosf(sig[tid + 1], &sn, &c);
            g_ab[tid] = make_float4(c, -sn, 2.f * sn, 0.f);
        }
        __syncthreads();
    }

    for (int i = tid; i < 80 * 64; i += 256) {
        int j = i / 64, f = i % 64;
        WsT[f][j] = Wp[i];
    }
    const float kdiv = -0.14391156831212787f;  // -ln(10000)/64
    for (int i = tid; i < 1024; i += 256) {
        int f = i >> 4, t = i & 15;
        float arg = (float)t * expf(kdiv * (float)(f & ~1));
        float pe = (f & 1) ? cosf(arg) : sinf(arg);
        xe[t][f] = x[b * 1024 + i] + pe;
    }
    __syncthreads();

    for (int o = tid; o < 1280; o += 256) {
        int t = o / 80, j = o % 80;
        float h = bp[j];
#pragma unroll 16
        for (int f = 0; f < 64; ++f) h = fmaf(xe[t][f], WsT[f][j], h);
        float half = 3.14159265358979323846f / (1.0f + expf(-h));
        float c, sn;
        sincosf(half, &sn, &c);
        g_csp[b * 1280 + o] = make_ulonglong2(f2pack(c, c), f2pack(sn, sn));
    }
}

// ---------------------------------------------------------------------------
// Rank-1 ancilla mix: s <- alpha*s + (beta*u0[w]) * dot,
// dot[q] = sum_t conj(u0[t]) * s_t[q].  4-way interleaved column sums.
// ---------------------------------------------------------------------------
static __device__ __forceinline__ void ancilla_mix_r1(f2x* s, f2x* buf, f2x* dot,
                                                      float2 u0w, float2 alpha, float b2s,
                                                      int w, int lane, int tid) {
    const f2x ccW = f2pack(u0w.x, u0w.x);
    const f2x pkW = f2pack(u0w.y, -u0w.y);
#pragma unroll
    for (int r = 0; r < 32; ++r)
        buf[w * 1024 + r * 32 + lane] = f2fma(ccW, s[r], f2mul(pkW, f2swap(s[r])));
    __syncthreads();
#pragma unroll 1
    for (int hh = 0; hh < 2; ++hh) {
        int q = hh * 512 + tid;
        f2x a0 = buf[q];
        f2x a1 = buf[1024 + q];
        f2x a2 = buf[2048 + q];
        f2x a3 = buf[3072 + q];
#pragma unroll
        for (int tt = 4; tt < 16; tt += 4) {
            a0 = f2add(a0, buf[tt * 1024 + q]);
            a1 = f2add(a1, buf[(tt + 1) * 1024 + q]);
            a2 = f2add(a2, buf[(tt + 2) * 1024 + q]);
            a3 = f2add(a3, buf[(tt + 3) * 1024 + q]);
        }
        dot[q] = f2add(f2add(a0, a1), f2add(a2, a3));
    }
    __syncthreads();
    const float gr = -b2s * u0w.y, gi = b2s * u0w.x;
    const f2x ccA = f2pack(alpha.x, alpha.x), pkA = f2pack(-alpha.y, alpha.y);
    const f2x ccG = f2pack(gr, gr), pkG = f2pack(-gi, gi);
#pragma unroll
    for (int r = 0; r < 32; ++r) {
        f2x d = dot[r * 32 + lane];
        f2x t = f2fma(ccG, d, f2mul(pkG, f2swap(d)));
        s[r] = f2fma(ccA, s[r], f2fma(pkA, f2swap(s[r]), t));
    }
}

// ---------------------------------------------------------------------------
// Main kernel: one CTA per batch element; warp w owns ancilla slice t=w.
// ---------------------------------------------------------------------------
__global__ __launch_bounds__(512, 1) void qts_main(const float* __restrict__ Wout,
                                                   const float* __restrict__ bout,
                                                   float* __restrict__ out) {
    extern __shared__ char smem_raw[];
    f2x* buf        = (f2x*)smem_raw;                       // [16][1024] (131072 B)
    f2x* dot        = (f2x*)(smem_raw + 131072);            // [1024] (8192 B)
    ulonglong2* sap = (ulonglong2*)(smem_raw + 139264);     // [16][80] packed (20480 B)
    ulonglong2* sqp = sap + 1280;                           // [40] packed qff
    float2* sv0     = (float2*)(sqp + 40);                  // [16]
    float2* su0     = sv0 + 16;                             // [16]
    float4* sab     = (float4*)(su0 + 16);                  // [3]
    float* acc      = (float*)(sab + 3);                    // [32]

    const int tid = threadIdx.x, b = blockIdx.x;
    const int w = tid >> 5, lane = tid & 31;

    for (int i = tid; i < 1280; i += 512) sap[i] = g_csp[b * 1280 + i];
    if (tid < 40) sqp[tid] = g_qffp[tid];
    if (tid < 16) { sv0[tid] = g_v0[tid]; su0[tid] = g_u0[tid]; }
    if (tid < 3) sab[tid] = g_ab[tid];
    if (tid < 30) acc[tid] = 0.f;
    __syncthreads();

    const ulonglong2* cs = sap + w * 80;
    const float2 u0w = su0[w];
    f2x s[32];

    // select k=0: first ry block on |0..0> is an exact product state (peel)
    {
        float lp = 1.f;
#pragma unroll
        for (int j = 0; j < 5; ++j) {
            ulonglong2 u = cs[2 * j + 1];
            lp *= ((lane >> j) & 1) ? f2lo(u.y) : f2lo(u.x);
        }
        float rp[32];
        rp[0] = lp;
#pragma unroll
        for (int j = 0; j < 5; ++j) {
            ulonglong2 u = cs[2 * j];
            float gc = f2lo(u.x), gs = f2lo(u.y);
            int m = 1 << j;
#pragma unroll
            for (int r = 0; r < 32; ++r)
                if (r < m) {
                    rp[r | m] = rp[r] * gs;
                    rp[r]     = rp[r] * gc;
                }
        }
        float2 v = sv0[w];
#pragma unroll
        for (int r = 0; r < 32; ++r) s[r] = f2pack(v.x * rp[r], v.y * rp[r]);

        run_layer_fwd_tail(s, cs, lane);
        run_layer_fwd(s, cs + 40, lane);
    }
    {
        float4 ab = sab[0];
        ancilla_mix_r1(s, buf, dot, u0w, make_float2(ab.x, ab.y), ab.z, w, lane, tid);
    }

    // k=1: adjoint select
    run_layer_adj(s, cs + 40, lane);
    run_layer_adj(s, cs, lane);
    {
        float4 ab = sab[1];
        ancilla_mix_r1(s, buf, dot, u0w, make_float2(ab.x, ab.y), ab.z, w, lane, tid);
    }

    // k=2: forward select
    run_layer_fwd(s, cs, lane);
    run_layer_fwd(s, cs + 40, lane);
    {
        float4 ab = sab[2];
        ancilla_mix_r1(s, buf, dot, u0w, make_float2(ab.x, ab.y), ab.z, w, lane, tid);
    }

    // k=3: adjoint select; trailing block-1 rys merged into qff's opening rys
    run_layer_adj(s, cs + 40, lane);
    run_layer_adj_nob1(s, cs, lane);
    run_qff_merged(s, cs, sqp, lane);

    expval_q<0>(s, lane, acc);
    expval_q<1>(s, lane, acc);
    expval_q<2>(s, lane, acc);
    expval_q<3>(s, lane, acc);
    expval_q<4>(s, lane, acc);
    expval_q<5>(s, lane, acc);
    expval_q<6>(s, lane, acc);
    expval_q<7>(s, lane, acc);
    expval_q<8>(s, lane, acc);
    expval_q<9>(s, lane, acc);
    __syncthreads();

    if (tid == 0) {
        float o = bout[0];
#pragma unroll
        for (int i = 0; i < 30; ++i) o = fmaf(acc[i], Wout[i], o);
        out[b] = o;
    }
}

// ---------------------------------------------------------------------------
extern "C" void kernel_launch(void* const* d_in, const int* in_sizes, int n_in,
                              void* d_out, int out_size) {
    (void)in_sizes; (void)n_in; (void)out_size;
    const float* x    = (const float*)d_in[0];
    const float* Wp   = (const float*)d_in[1];
    const float* bp   = (const float*)d_in[2];
    const float* prep = (const float*)d_in[3];
    const float* sig  = (const float*)d_in[4];
    const float* qff  = (const float*)d_in[5];
    const float* Wout = (const float*)d_in[6];
    const float* bout = (const float*)d_in[7];
    float* out = (float*)d_out;

    size_t smem = 139264 + 20480 + 40 * 16 + 16 * 8 + 16 * 8 + 3 * 16 + 32 * 4;
    cudaFuncSetAttribute(qts_main, cudaFuncAttributeMaxDynamicSharedMemorySize, (int)smem);

    qts_proj<<<BATCH, 256>>>(x, Wp, bp, prep, sig, qff);
    qts_main<<<BATCH, 512, smem>>>(Wout, bout, out);
}

// round 16
// speedup vs baseline: 1.0643x; 1.0643x over previous
#include <cuda_runtime.h>

// ---------------------------------------------------------------------------
// B=512, NQ=10, NA=4, T=16, DEG=4, LAYERS=2.
// Round-14 champion layout: 512 threads/CTA = 16 warps; warp w owns ancilla
// slice t=w; 1024 amps/warp = 32 f2x regs/lane. Alternating qubit map:
//   qubit Q even -> register bit Q/2 ; qubit Q odd -> lane bit Q/2.
// Ancilla mix M_k = alpha_k I + beta_k u0 u0^dag (rank-1).
// ry-merge: final adjoint ry block merged with qff's opening ry block.
// New this round: odd-qubit z expvals via one shared norm-sum S (drops the
// per-gate norm recompute from the five lane-qubit expval loops).
// ---------------------------------------------------------------------------

#define BATCH 512

typedef unsigned long long f2x;

__device__ float2 g_cs[BATCH * 1280];  // (cos,sin) half-angles per (b,t,gate)
__device__ float2 g_qffcs[40];
__device__ float2 g_v0[16];            // e^{i phi0} * U[:,0]
__device__ float2 g_u0[16];            // U[:,0]
__device__ float4 g_ab[3];             // (cos phi, -sin phi, 2 sin phi, 0)

// ---- f32x2 primitives ------------------------------------------------------
static __device__ __forceinline__ f2x f2pack(float lo, float hi) {
    f2x r; asm("mov.b64 %0, {%1, %2};" : "=l"(r) : "f"(lo), "f"(hi)); return r;
}
static __device__ __forceinline__ void f2unpack(f2x v, float& lo, float& hi) {
    asm("mov.b64 {%0, %1}, %2;" : "=f"(lo), "=f"(hi) : "l"(v));
}
static __device__ __forceinline__ f2x f2fma(f2x a, f2x b, f2x c) {
    f2x r; asm("fma.rn.f32x2 %0, %1, %2, %3;" : "=l"(r) : "l"(a), "l"(b), "l"(c)); return r;
}
static __device__ __forceinline__ f2x f2mul(f2x a, f2x b) {
    f2x r; asm("mul.rn.f32x2 %0, %1, %2;" : "=l"(r) : "l"(a), "l"(b)); return r;
}
static __device__ __forceinline__ f2x f2add(f2x a, f2x b) {
    f2x r; asm("add.rn.f32x2 %0, %1, %2;" : "=l"(r) : "l"(a), "l"(b)); return r;
}
static __device__ __forceinline__ f2x f2swap(f2x v) {
    float lo, hi; f2unpack(v, lo, hi); return f2pack(hi, lo);
}
static __device__ __forceinline__ f2x f2shfl(f2x v, int m) {
    float lo, hi; f2unpack(v, lo, hi);
    lo = __shfl_xor_sync(0xffffffffu, lo, m);
    hi = __shfl_xor_sync(0xffffffffu, hi, m);
    return f2pack(lo, hi);
}
static __device__ __forceinline__ f2x f2shflswap(f2x v, int m) {
    float lo, hi; f2unpack(v, lo, hi);
    lo = __shfl_xor_sync(0xffffffffu, lo, m);
    hi = __shfl_xor_sync(0xffffffffu, hi, m);
    return f2pack(hi, lo);
}
static __device__ __forceinline__ float2 cmulf(float2 a, float2 b) {
    return make_float2(a.x * b.x - a.y * b.y, a.x * b.y + a.y * b.x);
}

// ---- gates (round-9/14 forms; measured best) --------------------------------
template <int Q>
static __device__ __forceinline__ void ry_g(f2x* s, f2x cc, f2x sp, f2x ns, int lane) {
    if constexpr ((Q & 1) == 0) {
        constexpr int M = 1 << (Q / 2);
#pragma unroll
        for (int r = 0; r < 32; ++r)
            if (!(r & M)) {
                f2x a = s[r], b = s[r | M];
                s[r]     = f2fma(cc, a, f2mul(ns, b));
                s[r | M] = f2fma(cc, b, f2mul(sp, a));
            }
    } else {
        constexpr int L = 1 << (Q / 2);
        const f2x t = (lane & L) ? sp : ns;
#pragma unroll
        for (int r = 0; r < 32; ++r) {
            f2x o = f2shfl(s[r], L);
            s[r] = f2fma(cc, s[r], f2mul(t, o));
        }
    }
}

// crx (ctrl=1): new = c*own + sn*(other.y, -other.x); pk = (sn, -sn).
template <int C, int TQ>
static __device__ __forceinline__ void crx_g(f2x* s, f2x cc, f2x pk, int lane) {
    if constexpr ((C & 1) == 0 && (TQ & 1) == 1) {        // reg ctrl, lane tgt
        constexpr int MC = 1 << (C / 2), LT = 1 << (TQ / 2);
#pragma unroll
        for (int r = 0; r < 32; ++r)
            if (r & MC) {  // compile-time per r: shfl warp-uniform
                f2x osw = f2shflswap(s[r], LT);
                s[r] = f2fma(cc, s[r], f2mul(pk, osw));
            }
    } else {                                              // lane ctrl, reg tgt: no shfl
        constexpr int LC = 1 << (C / 2), MT = 1 << (TQ / 2);
        const bool act = (lane & LC) != 0;
        const f2x cc2 = act ? cc : f2pack(1.f, 1.f);
        const f2x pk2 = act ? pk : 0ull;
#pragma unroll
        for (int r = 0; r < 32; ++r)
            if (!(r & MT)) {
                f2x a = s[r], b = s[r | MT];
                s[r]      = f2fma(cc2, a, f2mul(pk2, f2swap(b)));
                s[r | MT] = f2fma(cc2, b, f2mul(pk2, f2swap(a)));
            }
    }
}

// ---- gate lists (order/indices validated rounds 4-14) ----------------------
#define RYM_F(Q, I)  { float2 g = cs[I]; f2x cc = f2pack(g.x, g.x), sp = f2pack(g.y, g.y), \
                       ns = f2pack(-g.y, -g.y); ry_g<Q>(s, cc, sp, ns, lane); }
#define RYM_A(Q, I)  { float2 g = cs[I]; f2x cc = f2pack(g.x, g.x), sp = f2pack(-g.y, -g.y), \
                       ns = f2pack(g.y, g.y); ry_g<Q>(s, cc, sp, ns, lane); }
#define CRXM_F(C, T, I) { float2 g = cs[I]; f2x cc = f2pack(g.x, g.x), pk = f2pack(g.y, -g.y); \
                          crx_g<C, T>(s, cc, pk, lane); }
#define CRXM_A(C, T, I) { float2 g = cs[I]; f2x cc = f2pack(g.x, g.x), pk = f2pack(-g.y, g.y); \
                          crx_g<C, T>(s, cc, pk, lane); }
// Merged ry: ry(phi_qff) * ry(-theta_sel) = ry(phi - theta).
#define RYM_C(Q, I)  { float2 a = cs[I]; float2 b = csq[I];                       \
                       float cm = fmaf(b.x, a.x, b.y * a.y);                      \
                       float sm = fmaf(b.y, a.x, -b.x * a.y);                     \
                       ry_g<Q>(s, f2pack(cm, cm), f2pack(sm, sm),                 \
                               f2pack(-sm, -sm), lane); }

#define GATES_TAIL(RYM, CRXM)                                                    \
    CRXM(9, 0, 10) CRXM(8, 9, 11) CRXM(7, 8, 12) CRXM(6, 7, 13) CRXM(5, 6, 14)  \
    CRXM(4, 5, 15) CRXM(3, 4, 16) CRXM(2, 3, 17) CRXM(1, 2, 18) CRXM(0, 1, 19)  \
    RYM(0, 20) RYM(1, 21) RYM(2, 22) RYM(3, 23) RYM(4, 24)                       \
    RYM(5, 25) RYM(6, 26) RYM(7, 27) RYM(8, 28) RYM(9, 29)                       \
    CRXM(9, 8, 30) CRXM(0, 9, 31) CRXM(1, 0, 32) CRXM(2, 1, 33) CRXM(3, 2, 34)  \
    CRXM(4, 3, 35) CRXM(5, 4, 36) CRXM(6, 5, 37) CRXM(7, 6, 38) CRXM(8, 7, 39)

#define GATES_FWD(RYM, CRXM)                                                     \
    RYM(0, 0) RYM(1, 1) RYM(2, 2) RYM(3, 3) RYM(4, 4)                            \
    RYM(5, 5) RYM(6, 6) RYM(7, 7) RYM(8, 8) RYM(9, 9)                            \
    GATES_TAIL(RYM, CRXM)

// Adjoint layer WITHOUT the trailing block-1 rys (merges into qff).
#define GATES_ADJ_NOB1(RYM, CRXM)                                                \
    CRXM(8, 7, 39) CRXM(7, 6, 38) CRXM(6, 5, 37) CRXM(5, 4, 36) CRXM(4, 3, 35)  \
    CRXM(3, 2, 34) CRXM(2, 1, 33) CRXM(1, 0, 32) CRXM(0, 9, 31) CRXM(9, 8, 30)  \
    RYM(9, 29) RYM(8, 28) RYM(7, 27) RYM(6, 26) RYM(5, 25)                       \
    RYM(4, 24) RYM(3, 23) RYM(2, 22) RYM(1, 21) RYM(0, 20)                       \
    CRXM(0, 1, 19) CRXM(1, 2, 18) CRXM(2, 3, 17) CRXM(3, 4, 16) CRXM(4, 5, 15)  \
    CRXM(5, 6, 14) CRXM(6, 7, 13) CRXM(7, 8, 12) CRXM(8, 9, 11) CRXM(9, 0, 10)

#define GATES_ADJ(RYM, CRXM)                                                     \
    GATES_ADJ_NOB1(RYM, CRXM)                                                    \
    RYM(9, 9) RYM(8, 8) RYM(7, 7) RYM(6, 6) RYM(5, 5)                            \
    RYM(4, 4) RYM(3, 3) RYM(2, 2) RYM(1, 1) RYM(0, 0)

static __device__ __forceinline__ void run_layer_fwd(f2x* s, const float2* cs, int lane) {
    GATES_FWD(RYM_F, CRXM_F)
}
static __device__ __forceinline__ void run_layer_fwd_tail(f2x* s, const float2* cs, int lane) {
    GATES_TAIL(RYM_F, CRXM_F)
}
static __device__ __forceinline__ void run_layer_adj(f2x* s, const float2* cs, int lane) {
    GATES_ADJ(RYM_A, CRXM_A)
}
static __device__ __forceinline__ void run_layer_adj_nob1(f2x* s, const float2* cs, int lane) {
    GATES_ADJ_NOB1(RYM_A, CRXM_A)
}
// qff with opening ry block merged with preceding adjoint block-1.
static __device__ __forceinline__ void run_qff_merged(f2x* s, const float2* csSel,
                                                      const float2* csq, int lane) {
    {
        const float2* cs = csSel;
        RYM_C(0, 0) RYM_C(1, 1) RYM_C(2, 2) RYM_C(3, 3) RYM_C(4, 4)
        RYM_C(5, 5) RYM_C(6, 6) RYM_C(7, 7) RYM_C(8, 8) RYM_C(9, 9)
    }
    {
        const float2* cs = csq;
        GATES_TAIL(RYM_F, CRXM_F)
    }
}

// ---- expectation values ----------------------------------------------------
// Even (register) qubits: full x,y,z in one pair loop (unchanged from r14).
template <int Q>
static __device__ __forceinline__ void expval_even(const f2x* s, int lane, float* acc) {
    constexpr int M = 1 << (Q / 2);
    float ax = 0.f, ay = 0.f, z = 0.f;
#pragma unroll
    for (int r = 0; r < 32; ++r)
        if (!(r & M)) {
            float axr, ayr, bxr, byr;
            f2unpack(s[r], axr, ayr);
            f2unpack(s[r | M], bxr, byr);
            ax = fmaf(axr, bxr, fmaf(ayr, byr, ax));
            ay = fmaf(axr, byr, fmaf(-ayr, bxr, ay));
            z  = fmaf(axr, axr, fmaf(ayr, ayr, fmaf(-bxr, bxr, fmaf(-byr, byr, z))));
        }
#pragma unroll
    for (int off = 16; off; off >>= 1) {
        ax += __shfl_xor_sync(0xffffffffu, ax, off);
        ay += __shfl_xor_sync(0xffffffffu, ay, off);
        z  += __shfl_xor_sync(0xffffffffu, z, off);
    }
    if (lane == 0) {
        atomicAdd(&acc[Q], 2.f * ax);
        atomicAdd(&acc[10 + Q], 2.f * ay);
        atomicAdd(&acc[20 + Q], z);
    }
}

// Odd (lane) qubits: x,y only (z handled via shared norm-sum S).
template <int Q>
static __device__ __forceinline__ void expval_odd_xy(const f2x* s, int lane, float* acc) {
    constexpr int L = 1 << (Q / 2);
    const bool lo = (lane & L) == 0;
    float ax = 0.f, ay = 0.f;
#pragma unroll
    for (int r = 0; r < 32; ++r) {
        float x, y;
        f2unpack(s[r], x, y);
        float ox = __shfl_xor_sync(0xffffffffu, x, L);
        float oy = __shfl_xor_sync(0xffffffffu, y, L);
        if (lo) {
            ax = fmaf(x, ox, fmaf(y, oy, ax));
            ay = fmaf(x, oy, fmaf(-y, ox, ay));
        }
    }
#pragma unroll
    for (int off = 16; off; off >>= 1) {
        ax += __shfl_xor_sync(0xffffffffu, ax, off);
        ay += __shfl_xor_sync(0xffffffffu, ay, off);
    }
    if (lane == 0) {
        atomicAdd(&acc[Q], 2.f * ax);
        atomicAdd(&acc[10 + Q], 2.f * ay);
    }
}

// ---------------------------------------------------------------------------
// Projection kernel (circuit-constant setup in block 0) — round-14 verbatim
// ---------------------------------------------------------------------------
__global__ void qts_proj(const float* __restrict__ x, const float* __restrict__ Wp,
                         const float* __restrict__ bp, const float* __restrict__ prep,
                         const float* __restrict__ sig, const float* __restrict__ qff) {
    __shared__ float xe[16][64];
    __shared__ float WsT[64][80];
    __shared__ float2 U[16][16];
    int b = blockIdx.x, tid = threadIdx.x;

    if (b == 0) {
        if (tid < 16) {
            float2 v[16];
            for (int t = 0; t < 16; ++t) v[t] = make_float2(t == tid ? 1.f : 0.f, 0.f);
            for (int ly = 0; ly < 4; ++ly) {
                for (int qi = 0; qi < 4; ++qi) {
                    int m = 1 << (3 - qi);
                    float th = prep[(ly * 4 + qi) * 2 + 0];
                    float c, sn;
                    sincosf(0.5f * th, &sn, &c);
                    for (int j = 0; j < 16; ++j)
                        if (!(j & m)) {
                            float2 a0 = v[j], a1 = v[j | m];
                            v[j]     = make_float2(c * a0.x - sn * a1.x, c * a0.y - sn * a1.y);
                            v[j | m] = make_float2(sn * a0.x + c * a1.x, sn * a0.y + c * a1.y);
                        }
                    th = prep[(ly * 4 + qi) * 2 + 1];
                    sincosf(0.5f * th, &sn, &c);
                    float2 e0 = make_float2(c, -sn), e1 = make_float2(c, sn);
                    for (int j = 0; j < 16; ++j) v[j] = cmulf(v[j], (j & m) ? e1 : e0);
                }
                for (int i = 0; i < 3; ++i) {
                    int cm = 1 << (3 - i), tm = 1 << (2 - i);
                    for (int j = 0; j < 16; ++j)
                        if ((j & cm) && !(j & tm)) {
                            float2 tmp = v[j]; v[j] = v[j | tm]; v[j | tm] = tmp;
                        }
                }
            }
            for (int t = 0; t < 16; ++t) U[t][tid] = v[t];
        }
        __syncthreads();
        if (tid < 16) {
            float c, sn;
            sincosf(sig[0], &sn, &c);
            g_v0[tid] = cmulf(make_float2(c, sn), U[tid][0]);
            g_u0[tid] = U[tid][0];
        }
        if (tid < 40) {
            float c, sn;
            sincosf(0.5f * qff[tid], &sn, &c);
            g_qffcs[tid] = make_float2(c, sn);
        }
        if (tid < 3) {
            float c, sn;
            sincosf(sig[tid + 1], &sn, &c);
            g_ab[tid] = make_float4(c, -sn, 2.f * sn, 0.f);
        }
        __syncthreads();
    }

    for (int i = tid; i < 80 * 64; i += 256) {
        int j = i / 64, f = i % 64;
        WsT[f][j] = Wp[i];
    }
    const float kdiv = -0.14391156831212787f;  // -ln(10000)/64
    for (int i = tid; i < 1024; i += 256) {
        int f = i >> 4, t = i & 15;
        float arg = (float)t * expf(kdiv * (float)(f & ~1));
        float pe = (f & 1) ? cosf(arg) : sinf(arg);
        xe[t][f] = x[b * 1024 + i] + pe;
    }
    __syncthreads();

    for (int o = tid; o < 1280; o += 256) {
        int t = o / 80, j = o % 80;
        float h = bp[j];
#pragma unroll 16
        for (int f = 0; f < 64; ++f) h = fmaf(xe[t][f], WsT[f][j], h);
        float half = 3.14159265358979323846f / (1.0f + expf(-h));
        float c, sn;
        sincosf(half, &sn, &c);
        g_cs[b * 1280 + o] = make_float2(c, sn);
    }
}

// ---------------------------------------------------------------------------
// Rank-1 ancilla mix: s <- alpha*s + (beta*u0[w]) * dot,
// dot[q] = sum_t conj(u0[t]) * s_t[q].  4-way interleaved column sums.
// ---------------------------------------------------------------------------
static __device__ __forceinline__ void ancilla_mix_r1(f2x* s, f2x* buf, f2x* dot,
                                                      float2 u0w, float2 alpha, float b2s,
                                                      int w, int lane, int tid) {
    const f2x ccW = f2pack(u0w.x, u0w.x);
    const f2x pkW = f2pack(u0w.y, -u0w.y);
#pragma unroll
    for (int r = 0; r < 32; ++r)
        buf[w * 1024 + r * 32 + lane] = f2fma(ccW, s[r], f2mul(pkW, f2swap(s[r])));
    __syncthreads();
#pragma unroll 1
    for (int hh = 0; hh < 2; ++hh) {
        int q = hh * 512 + tid;
        f2x a0 = buf[q];
        f2x a1 = buf[1024 + q];
        f2x a2 = buf[2048 + q];
        f2x a3 = buf[3072 + q];
#pragma unroll
        for (int tt = 4; tt < 16; tt += 4) {
            a0 = f2add(a0, buf[tt * 1024 + q]);
            a1 = f2add(a1, buf[(tt + 1) * 1024 + q]);
            a2 = f2add(a2, buf[(tt + 2) * 1024 + q]);
            a3 = f2add(a3, buf[(tt + 3) * 1024 + q]);
        }
        dot[q] = f2add(f2add(a0, a1), f2add(a2, a3));
    }
    __syncthreads();
    const float gr = -b2s * u0w.y, gi = b2s * u0w.x;
    const f2x ccA = f2pack(alpha.x, alpha.x), pkA = f2pack(-alpha.y, alpha.y);
    const f2x ccG = f2pack(gr, gr), pkG = f2pack(-gi, gi);
#pragma unroll
    for (int r = 0; r < 32; ++r) {
        f2x d = dot[r * 32 + lane];
        f2x t = f2fma(ccG, d, f2mul(pkG, f2swap(d)));
        s[r] = f2fma(ccA, s[r], f2fma(pkA, f2swap(s[r]), t));
    }
}

// ---------------------------------------------------------------------------
// Main kernel: one CTA per batch element; warp w owns ancilla slice t=w.
// ---------------------------------------------------------------------------
__global__ __launch_bounds__(512, 1) void qts_main(const float* __restrict__ Wout,
                                                   const float* __restrict__ bout,
                                                   float* __restrict__ out) {
    extern __shared__ char smem_raw[];
    f2x* buf     = (f2x*)smem_raw;                        // [16][1024] (131072 B)
    f2x* dot     = (f2x*)(smem_raw + 131072);             // [1024] (8192 B)
    float2* sa   = (float2*)(smem_raw + 131072 + 8192);   // [16][80] (10240 B)
    float2* sqff = sa + 1280;                             // [40]
    float2* sv0  = sqff + 40;                             // [16]
    float2* su0  = sv0 + 16;                              // [16]
    float4* sab  = (float4*)(su0 + 16);                   // [3]
    float* acc   = (float*)(sab + 3);                     // [32]

    const int tid = threadIdx.x, b = blockIdx.x;
    const int w = tid >> 5, lane = tid & 31;

    for (int i = tid; i < 1280; i += 512) sa[i] = g_cs[b * 1280 + i];
    if (tid < 40) sqff[tid] = g_qffcs[tid];
    if (tid < 16) { sv0[tid] = g_v0[tid]; su0[tid] = g_u0[tid]; }
    if (tid < 3) sab[tid] = g_ab[tid];
    if (tid < 30) acc[tid] = 0.f;
    __syncthreads();

    const float2* cs = sa + w * 80;
    const float2 u0w = su0[w];
    f2x s[32];

    // select k=0: first ry block on |0..0> is an exact product state (peel)
    {
        float lp = 1.f;
#pragma unroll
        for (int j = 0; j < 5; ++j) {
            float2 g = cs[2 * j + 1];
            lp *= ((lane >> j) & 1) ? g.y : g.x;
        }
        float rp[32];
        rp[0] = lp;
#pragma unroll
        for (int j = 0; j < 5; ++j) {
            float2 g = cs[2 * j];
            int m = 1 << j;
#pragma unroll
            for (int r = 0; r < 32; ++r)
                if (r < m) {
                    rp[r | m] = rp[r] * g.y;
                    rp[r]     = rp[r] * g.x;
                }
        }
        float2 v = sv0[w];
#pragma unroll
        for (int r = 0; r < 32; ++r) s[r] = f2pack(v.x * rp[r], v.y * rp[r]);

        run_layer_fwd_tail(s, cs, lane);
        run_layer_fwd(s, cs + 40, lane);
    }
    {
        float4 ab = sab[0];
        ancilla_mix_r1(s, buf, dot, u0w, make_float2(ab.x, ab.y), ab.z, w, lane, tid);
    }

    // k=1: adjoint select
    run_layer_adj(s, cs + 40, lane);
    run_layer_adj(s, cs, lane);
    {
        float4 ab = sab[1];
        ancilla_mix_r1(s, buf, dot, u0w, make_float2(ab.x, ab.y), ab.z, w, lane, tid);
    }

    // k=2: forward select
    run_layer_fwd(s, cs, lane);
    run_layer_fwd(s, cs + 40, lane);
    {
        float4 ab = sab[2];
        ancilla_mix_r1(s, buf, dot, u0w, make_float2(ab.x, ab.y), ab.z, w, lane, tid);
    }

    // k=3: adjoint select; trailing block-1 rys merged into qff's opening rys
    run_layer_adj(s, cs + 40, lane);
    run_layer_adj_nob1(s, cs, lane);
    run_qff_merged(s, cs, sqff, lane);

    // ---- expectation values ----
    // Shared norm-sum: S = sum_r |s_r|^2 per lane; odd-qubit z = +-S reduced.
    {
        float S = 0.f;
#pragma unroll
        for (int r = 0; r < 32; ++r) {
            float x, y;
            f2unpack(s[r], x, y);
            S = fmaf(x, x, fmaf(y, y, S));
        }
        float z1 = (lane & 1) ? -S : S;
        float z3 = (lane & 2) ? -S : S;
        float z5 = (lane & 4) ? -S : S;
        float z7 = (lane & 8) ? -S : S;
        float z9 = (lane & 16) ? -S : S;
#pragma unroll
        for (int off = 16; off; off >>= 1) {
            z1 += __shfl_xor_sync(0xffffffffu, z1, off);
            z3 += __shfl_xor_sync(0xffffffffu, z3, off);
            z5 += __shfl_xor_sync(0xffffffffu, z5, off);
            z7 += __shfl_xor_sync(0xffffffffu, z7, off);
            z9 += __shfl_xor_sync(0xffffffffu, z9, off);
        }
        if (lane == 0) {
            atomicAdd(&acc[21], z1);
            atomicAdd(&acc[23], z3);
            atomicAdd(&acc[25], z5);
            atomicAdd(&acc[27], z7);
            atomicAdd(&acc[29], z9);
        }
    }
    expval_even<0>(s, lane, acc);
    expval_even<2>(s, lane, acc);
    expval_even<4>(s, lane, acc);
    expval_even<6>(s, lane, acc);
    expval_even<8>(s, lane, acc);
    expval_odd_xy<1>(s, lane, acc);
    expval_odd_xy<3>(s, lane, acc);
    expval_odd_xy<5>(s, lane, acc);
    expval_odd_xy<7>(s, lane, acc);
    expval_odd_xy<9>(s, lane, acc);
    __syncthreads();

    if (tid == 0) {
        float o = bout[0];
#pragma unroll
        for (int i = 0; i < 30; ++i) o = fmaf(acc[i], Wout[i], o);
        out[b] = o;
    }
}

// ---------------------------------------------------------------------------
extern "C" void kernel_launch(void* const* d_in, const int* in_sizes, int n_in,
                              void* d_out, int out_size) {
    (void)in_sizes; (void)n_in; (void)out_size;
    const float* x    = (const float*)d_in[0];
    const float* Wp   = (const float*)d_in[1];
    const float* bp   = (const float*)d_in[2];
    const float* prep = (const float*)d_in[3];
    const float* sig  = (const float*)d_in[4];
    const float* qff  = (const float*)d_in[5];
    const float* Wout = (const float*)d_in[6];
    const float* bout = (const float*)d_in[7];
    float* out = (float*)d_out;

    size_t smem = 131072 + 8192 + 10240 + 40 * 8 + 16 * 8 + 16 * 8 + 3 * 16 + 32 * 4;
    cudaFuncSetAttribute(qts_main, cudaFuncAttributeMaxDynamicSharedMemorySize, (int)smem);

    qts_proj<<<BATCH, 256>>>(x, Wp, bp, prep, sig, qff);
    qts_main<<<BATCH, 512, smem>>>(Wout, bout, out);
}